// round 17
// baseline (speedup 1.0000x reference)
#include <cuda_runtime.h>
#include <cuda_bf16.h>
#include <cstdint>

typedef unsigned long long ULL;

__device__ __forceinline__ uint32_t smem_u32(const void* p) {
    uint32_t a;
    asm("{ .reg .u64 t; cvta.to.shared.u64 t, %1; cvt.u32.u64 %0, t; }"
        : "=r"(a) : "l"(p));
    return a;
}

// ---------------------------------------------------------------------------
// Scratch (device globals — no allocation allowed). 16B-aligned.
// ---------------------------------------------------------------------------
#define MAX_LOC 100000
#define MAX_EVT 200000

__device__ __align__(16) float g_evt[(size_t)MAX_EVT * 64];
__device__ __align__(16) float g_loc[(size_t)MAX_LOC * 64];
__device__ __align__(16) float g_msg[(size_t)MAX_LOC * 64];
__device__ __align__(16) float g_cnt[MAX_LOC];
__device__ int g_idx32;

// Pre-split weight images (bf16 hi/lo, already in swizzled smem layout):
__device__ __align__(16) uint32_t g_wp[2][2][4096];  // [which][hi/lo] proj W^T
__device__ __align__(16) uint32_t g_ws[2][4096];     // [hi/lo] stacked [Wl;Wr]^T
__device__ __align__(16) uint32_t g_wh[2][1024];     // [hi/lo] Wh1^T

// ---------------------------------------------------------------------------
// bf16 hi/lo split, 6 instrs/pair (R16, verified).
// ---------------------------------------------------------------------------
__device__ __forceinline__ void bf16split(float a, float b,
                                          uint32_t& hw, uint32_t& lw) {
    __nv_bfloat162 h = __float22bfloat162_rn(make_float2(a, b));
    hw = *(uint32_t*)&h;
    float ah = __uint_as_float(hw << 16);
    float bh = __uint_as_float(hw & 0xFFFF0000u);
    __nv_bfloat162 l = __float22bfloat162_rn(make_float2(a - ah, b - bh));
    lw = *(uint32_t*)&l;
}

// ---------------------------------------------------------------------------
// Prep launch: dtype detect + pre-split all weights (52 blocks + 1).
// Zeroing has moved into the proj_evt launch (overlap).
// ---------------------------------------------------------------------------
__global__ void prep_kernel(const long long* __restrict__ ei,
                            const float* __restrict__ Wloc,
                            const float* __restrict__ Wevt,
                            const float* __restrict__ Wl,
                            const float* __restrict__ Wr,
                            const float* __restrict__ Wh1)
{
    int j = (int)blockIdx.x * 256 + threadIdx.x;
    if (j == 13312) {                     // one thread: dtype detect
        int is32 = 0;
#pragma unroll 8
        for (int k = 0; k < 256; k++) {
            ULL v = (ULL)ei[k];
            if (v >= 0x100000000ULL) is32 = 1;
        }
        g_idx32 = is32;
        return;
    }
    if (j < 8192) {                       // proj weights: 2 matrices
        int which = j >> 12, p = j & 4095;
        int kp = p >> 6, n = p & 63;
        const float* W = which ? Wevt : Wloc;
        float w0 = W[(2 * kp) * 64 + n];
        float w1 = W[(2 * kp + 1) * 64 + n];
        uint32_t hw, lw;
        bf16split(w0, w1, hw, lw);
        uint32_t word = (uint32_t)n * 64 + (((kp >> 2) ^ (n & 7)) * 4) + (kp & 3);
        g_wp[which][0][word] = hw;
        g_wp[which][1][word] = lw;
    } else if (j < 12288) {               // stacked [Wl ; Wr]^T
        int p = j - 8192;
        int kp = p >> 6, n = p & 63;
        int k0 = 2 * kp;
        float w0 = (k0 < 64) ? Wl[k0 * 64 + n] : Wr[(k0 - 64) * 64 + n];
        float w1 = (k0 < 64) ? Wl[(k0 + 1) * 64 + n] : Wr[(k0 - 63) * 64 + n];
        uint32_t hw, lw;
        bf16split(w0, w1, hw, lw);
        uint32_t word = (uint32_t)n * 64 + (((kp >> 2) ^ (n & 7)) * 4) + (kp & 3);
        g_ws[0][word] = hw;
        g_ws[1][word] = lw;
    } else if (j < 13312) {               // Wh1^T
        int p = j - 12288;
        int kp = p >> 5, n = p & 31;
        float w0 = Wh1[(2 * kp) * 32 + n];
        float w1 = Wh1[(2 * kp + 1) * 32 + n];
        uint32_t hw, lw;
        bf16split(w0, w1, hw, lw);
        uint32_t word = (uint32_t)n * 32 + (((kp >> 2) ^ (n & 7)) * 4) + (kp & 3);
        g_wh[0][word] = hw;
        g_wh[1][word] = lw;
    }
}

// ---------------------------------------------------------------------------
// mma.sync helpers (verified R8+)
// ---------------------------------------------------------------------------
__device__ __forceinline__ void ldsm_x4(uint32_t& r0, uint32_t& r1,
                                        uint32_t& r2, uint32_t& r3, uint32_t addr) {
    asm volatile("ldmatrix.sync.aligned.m8n8.x4.shared.b16 {%0,%1,%2,%3}, [%4];"
                 : "=r"(r0), "=r"(r1), "=r"(r2), "=r"(r3) : "r"(addr));
}
__device__ __forceinline__ void mma16816(float* c, const uint32_t* a,
                                         uint32_t b0, uint32_t b1) {
    asm volatile(
        "mma.sync.aligned.m16n8k16.row.col.f32.bf16.bf16.f32 "
        "{%0,%1,%2,%3}, {%4,%5,%6,%7}, {%8,%9}, {%0,%1,%2,%3};"
        : "+f"(c[0]), "+f"(c[1]), "+f"(c[2]), "+f"(c[3])
        : "r"(a[0]), "r"(a[1]), "r"(a[2]), "r"(a[3]), "r"(b0), "r"(b1));
}

// ---------------------------------------------------------------------------
// Projection tile (device fn; body identical to R16 proj_mma_kernel).
// ---------------------------------------------------------------------------
#define XH_OFF 256
#define XL_OFF (XH_OFF + 16384)
#define WH_OFF (XL_OFF + 16384)
#define WL_OFF (WH_OFF + 16384)
#define PROJ_SMEM (WL_OFF + 16384)   // 65792 B -> 3 CTAs/SM

__device__ __forceinline__ void proj_tile(
    char* sm, uint32_t sb, const float* __restrict__ x,
    const float* __restrict__ bias, float* __restrict__ out,
    int N, int rowBase, int which)
{
    float* sbias = (float*)sm;
    const int tid = threadIdx.x;
    const int lane = tid & 31;
    const int w = tid >> 5;

    if (tid < 64) sbias[tid] = bias[tid];

    {
        const uint4* srcH = (const uint4*)g_wp[which][0];
        const uint4* srcL = (const uint4*)g_wp[which][1];
        uint4* dstH = (uint4*)(sm + WH_OFF);
        uint4* dstL = (uint4*)(sm + WL_OFF);
#pragma unroll
        for (int i = 0; i < 4; i++) {
            dstH[tid + 256 * i] = srcH[tid + 256 * i];
            dstL[tid + 256 * i] = srcL[tid + 256 * i];
        }
    }

    const int warpRow = (w >> 1) * 32;
    const int warpCol = (w & 1) * 32;

    float acc[2][4][4];
#pragma unroll
    for (int mi = 0; mi < 2; mi++)
#pragma unroll
        for (int nb = 0; nb < 4; nb++)
#pragma unroll
            for (int c = 0; c < 4; c++) acc[mi][nb][c] = 0.0f;

    const int aRow = warpRow + (lane & 15);
    const int aKh  = lane >> 4;
    const int bN   = warpCol + ((lane >> 4) << 3) + (lane & 7);
    const int bKh  = (lane >> 3) & 1;

    for (int h = 0; h < 2; h++) {
        if (h) __syncthreads();

#pragma unroll
        for (int j = 0; j < 4; j++) {
            int g = tid + 256 * j;
            int r = g >> 3, u = g & 7;
            int row = rowBase + r;
            if (row >= N) row = N - 1;
            const float4* src = (const float4*)&x[(long)row * 128 + h * 64 + u * 8];
            float4 v0 = src[0];
            float4 v1 = src[1];
            uint4 hiw, low;
            bf16split(v0.x, v0.y, hiw.x, low.x);
            bf16split(v0.z, v0.w, hiw.y, low.y);
            bf16split(v1.x, v1.y, hiw.z, low.z);
            bf16split(v1.z, v1.w, hiw.w, low.w);
            uint32_t off = (uint32_t)r * 128 + ((u ^ (r & 7)) * 16);
            *(uint4*)(sm + XH_OFF + off) = hiw;
            *(uint4*)(sm + XL_OFF + off) = low;
        }
        __syncthreads();

        for (int seg = 0; seg < 3; seg++) {
            const uint32_t aBase = sb + ((seg == 2) ? XL_OFF : XH_OFF);
            const uint32_t bBase = sb + ((seg == 1) ? WL_OFF : WH_OFF);
#pragma unroll
            for (int k16l = 0; k16l < 4; k16l++) {
                const int k16g = h * 4 + k16l;
                uint32_t a[2][4], b[4][2];
#pragma unroll
                for (int mi = 0; mi < 2; mi++) {
                    int r = aRow + mi * 16;
                    uint32_t addr = aBase + (uint32_t)r * 128 +
                                    (uint32_t)(((k16l * 2 + aKh) ^ (r & 7)) * 16);
                    ldsm_x4(a[mi][0], a[mi][1], a[mi][2], a[mi][3], addr);
                }
#pragma unroll
                for (int ni2 = 0; ni2 < 2; ni2++) {
                    int n = bN + ni2 * 16;
                    uint32_t addr = bBase + (uint32_t)n * 256 +
                                    (uint32_t)(((k16g * 2 + bKh) ^ (n & 7)) * 16);
                    ldsm_x4(b[ni2 * 2][0], b[ni2 * 2][1],
                            b[ni2 * 2 + 1][0], b[ni2 * 2 + 1][1], addr);
                }
#pragma unroll
                for (int mi = 0; mi < 2; mi++)
#pragma unroll
                    for (int nb = 0; nb < 4; nb++)
                        mma16816(acc[mi][nb], a[mi], b[nb][0], b[nb][1]);
            }
        }
    }

#pragma unroll
    for (int mi = 0; mi < 2; mi++) {
#pragma unroll
        for (int part = 0; part < 2; part++) {
            int row = rowBase + warpRow + mi * 16 + (lane >> 2) + part * 8;
            if (row < N) {
                float* orow = out + (long)row * 64;
#pragma unroll
                for (int nb = 0; nb < 4; nb++) {
                    int col = warpCol + nb * 8 + (lane & 3) * 2;
                    float2 o;
                    o.x = fmaxf(acc[mi][nb][part * 2 + 0] + sbias[col], 0.0f);
                    o.y = fmaxf(acc[mi][nb][part * 2 + 1] + sbias[col + 1], 0.0f);
                    *(float2*)&orow[col] = o;
                }
            }
        }
    }
}

// ---------------------------------------------------------------------------
// Scatter body (device fn; identical math to R16 scatter_kernel) for a
// local block index.
// ---------------------------------------------------------------------------
__device__ __forceinline__ void scatter_body(const long long* __restrict__ ei,
                                             int E, int NL, int sbid)
{
    long gid = (long)sbid * 256 + threadIdx.x;
    int g4 = (int)(gid >> 4);
    int q  = (int)(gid & 15);
    int e0 = g4 * 4;
    if (e0 >= E) return;
    const int idx32 = g_idx32;
    const int ne = (E - e0 < 4) ? (E - e0) : 4;

    int s[4], d[4];
#pragma unroll
    for (int j = 0; j < 4; j++) {
        int e = e0 + ((j < ne) ? j : 0);
        if (idx32) {
            const int* e32 = (const int*)ei;
            s[j] = e32[e];
            d[j] = e32[E + e];
        } else {
            s[j] = (int)ei[e];
            d[j] = (int)ei[(long)E + e];
        }
    }

    bool ok[4];
    float4 v[4];
#pragma unroll
    for (int j = 0; j < 4; j++) {
        ok[j] = (j < ne) && (unsigned)s[j] < (unsigned)MAX_EVT &&
                (unsigned)d[j] < (unsigned)NL;
        v[j] = ok[j] ? *(const float4*)&g_evt[(long)s[j] * 64 + q * 4]
                     : make_float4(0.f, 0.f, 0.f, 0.f);
    }
#pragma unroll
    for (int j = 0; j < 4; j++) {
        if (ok[j]) {
            atomicAdd((float4*)&g_msg[(long)d[j] * 64 + q * 4], v[j]);
            if (q == 0) atomicAdd(&g_cnt[d[j]], 1.0f);
        }
    }
}

// ---------------------------------------------------------------------------
// K2: proj(evt) blocks [0, nB) ∥ zero blocks [nB, nB+zb).
// ---------------------------------------------------------------------------
__global__ __launch_bounds__(256, 3) void proj_evt_zero_kernel(
    const float* __restrict__ xb, const float* __restrict__ bb,
    int Nb, int nB, int n4, int NL)
{
    extern __shared__ __align__(16) char sm[];
    if ((int)blockIdx.x < nB) {
        proj_tile(sm, smem_u32(sm), xb, bb, g_evt, Nb, blockIdx.x * 128, 1);
    } else {
        int i = ((int)blockIdx.x - nB) * 256 + threadIdx.x;
        if (i < n4) ((float4*)g_msg)[i] = make_float4(0.f, 0.f, 0.f, 0.f);
        if (i < NL) g_cnt[i] = 0.0f;
    }
}

// ---------------------------------------------------------------------------
// K3: proj(loc) blocks [0, nA) ∥ scatter blocks [nA, nA+scB).
// Disjoint pipes (tensor/LDSM vs L2 atomics) -> co-residency fills the SM.
// ---------------------------------------------------------------------------
__global__ __launch_bounds__(256, 3) void proj_loc_scatter_kernel(
    const float* __restrict__ xa, const float* __restrict__ ba,
    int Na, int nA, const long long* __restrict__ ei, int E, int NL)
{
    extern __shared__ __align__(16) char sm[];
    if ((int)blockIdx.x < nA) {
        proj_tile(sm, smem_u32(sm), xa, ba, g_loc, Na, blockIdx.x * 128, 0);
    } else {
        scatter_body(ei, E, NL, (int)blockIdx.x - nA);
    }
}

// ---------------------------------------------------------------------------
// Fused SAGE + head via mma.sync (unchanged R16).
// ---------------------------------------------------------------------------
#define F_BL   0
#define F_BH1  256
#define F_WH2  384
#define F_BH2  512
#define F_XH   768
#define F_XL   (F_XH + 16384)
#define F_WH   (F_XL + 16384)
#define F_WL   (F_WH + 16384)
#define F_H1H  (F_WL + 16384)
#define F_H1L  (F_H1H + 4096)
#define FUSEDM_SMEM (F_H1L + 4096)   // 74496 B -> 3 CTAs/SM

__global__ __launch_bounds__(256, 3) void fused_mma_kernel(
    const float* __restrict__ bl, const float* __restrict__ bh1,
    const float* __restrict__ Wh2, const float* __restrict__ bh2,
    float* __restrict__ out, int N)
{
    extern __shared__ __align__(16) char sm[];
    const uint32_t sb = smem_u32(sm);
    float* sbl  = (float*)(sm + F_BL);
    float* sbh1 = (float*)(sm + F_BH1);
    float* swh2 = (float*)(sm + F_WH2);
    float* sbh2 = (float*)(sm + F_BH2);

    const int tid = threadIdx.x;
    const int lane = tid & 31;
    const int w = tid >> 5;
    const int rowBase = blockIdx.x * 128;

    if (tid < 64) sbl[tid] = bl[tid];
    if (tid < 32) { sbh1[tid] = bh1[tid]; swh2[tid] = Wh2[tid]; }
    if (tid == 0) sbh2[0] = bh2[0];

    {
        const uint4* sH = (const uint4*)g_ws[0];
        const uint4* sL = (const uint4*)g_ws[1];
        uint4* dH = (uint4*)(sm + F_WH);
        uint4* dL = (uint4*)(sm + F_WL);
#pragma unroll
        for (int i = 0; i < 4; i++) {
            dH[tid + 256 * i] = sH[tid + 256 * i];
            dL[tid + 256 * i] = sL[tid + 256 * i];
        }
        ((uint4*)(sm + F_H1H))[tid] = ((const uint4*)g_wh[0])[tid];
        ((uint4*)(sm + F_H1L))[tid] = ((const uint4*)g_wh[1])[tid];
    }

    const int warpRow = (w >> 1) * 32;
    const int warpCol = (w & 1) * 32;

    float acc[2][4][4];
#pragma unroll
    for (int mi = 0; mi < 2; mi++)
#pragma unroll
        for (int nb = 0; nb < 4; nb++)
#pragma unroll
            for (int c = 0; c < 4; c++) acc[mi][nb][c] = 0.0f;

    const int aRow = warpRow + (lane & 15);
    const int aKh  = lane >> 4;
    const int bN   = warpCol + ((lane >> 4) << 3) + (lane & 7);
    const int bKh  = (lane >> 3) & 1;

    for (int h = 0; h < 2; h++) {
        if (h) __syncthreads();

#pragma unroll
        for (int j = 0; j < 4; j++) {
            int g = tid + 256 * j;
            int r = g >> 3, u = g & 7;
            int row = rowBase + r;
            if (row >= N) row = N - 1;
            float4 v0, v1;
            if (h == 0) {
                float inv = 1.0f / fmaxf(g_cnt[row], 1.0f);
                const float4* src = (const float4*)&g_msg[(long)row * 64 + u * 8];
                v0 = src[0]; v1 = src[1];
                v0.x *= inv; v0.y *= inv; v0.z *= inv; v0.w *= inv;
                v1.x *= inv; v1.y *= inv; v1.z *= inv; v1.w *= inv;
            } else {
                const float4* src = (const float4*)&g_loc[(long)row * 64 + u * 8];
                v0 = src[0]; v1 = src[1];
            }
            uint4 hiw, low;
            bf16split(v0.x, v0.y, hiw.x, low.x);
            bf16split(v0.z, v0.w, hiw.y, low.y);
            bf16split(v1.x, v1.y, hiw.z, low.z);
            bf16split(v1.z, v1.w, hiw.w, low.w);
            uint32_t off = (uint32_t)r * 128 + ((u ^ (r & 7)) * 16);
            *(uint4*)(sm + F_XH + off) = hiw;
            *(uint4*)(sm + F_XL + off) = low;
        }
        __syncthreads();

        for (int seg = 0; seg < 3; seg++) {
            const uint32_t aBase = sb + ((seg == 2) ? F_XL : F_XH);
            const uint32_t bBase = sb + ((seg == 1) ? F_WL : F_WH);
#pragma unroll
            for (int k16l = 0; k16l < 4; k16l++) {
                const int k16g = h * 4 + k16l;
                uint32_t a[2][4], b[4][2];
#pragma unroll
                for (int mi = 0; mi < 2; mi++) {
                    int r = aRow + mi * 16;
                    uint32_t addr = aBase + (uint32_t)r * 128 +
                                    (uint32_t)(((k16l * 2 + aKh) ^ (r & 7)) * 16);
                    ldsm_x4(a[mi][0], a[mi][1], a[mi][2], a[mi][3], addr);
                }
#pragma unroll
                for (int ni2 = 0; ni2 < 2; ni2++) {
                    int n = bN + ni2 * 16;
                    uint32_t addr = bBase + (uint32_t)n * 256 +
                                    (uint32_t)(((k16g * 2 + bKh) ^ (n & 7)) * 16);
                    ldsm_x4(b[ni2 * 2][0], b[ni2 * 2][1],
                            b[ni2 * 2 + 1][0], b[ni2 * 2 + 1][1], addr);
                }
#pragma unroll
                for (int mi = 0; mi < 2; mi++)
#pragma unroll
                    for (int nb = 0; nb < 4; nb++)
                        mma16816(acc[mi][nb], a[mi], b[nb][0], b[nb][1]);
            }
        }
    }

    __syncthreads();
#pragma unroll
    for (int mi = 0; mi < 2; mi++) {
#pragma unroll
        for (int part = 0; part < 2; part++) {
            int r = warpRow + mi * 16 + (lane >> 2) + part * 8;
#pragma unroll
            for (int nb = 0; nb < 4; nb++) {
                int col = warpCol + nb * 8 + (lane & 3) * 2;
                float z0 = fmaxf(acc[mi][nb][part * 2 + 0] + sbl[col], 0.0f);
                float z1 = fmaxf(acc[mi][nb][part * 2 + 1] + sbl[col + 1], 0.0f);
                uint32_t hw, lw;
                bf16split(z0, z1, hw, lw);
                uint32_t off = (uint32_t)r * 128 +
                               (((col >> 3) ^ (r & 7)) * 16) + (col & 7) * 2;
                *(uint32_t*)(sm + F_XH + off) = hw;
                *(uint32_t*)(sm + F_XL + off) = lw;
            }
        }
    }
    __syncthreads();

    const int aRowH = w * 16 + (lane & 15);
    const int bNh   = ((lane >> 4) << 3) + (lane & 7);

    float hacc[4][4];
#pragma unroll
    for (int nb = 0; nb < 4; nb++)
#pragma unroll
        for (int c = 0; c < 4; c++) hacc[nb][c] = 0.0f;

    for (int seg = 0; seg < 3; seg++) {
        const uint32_t aBase = sb + ((seg == 2) ? F_XL : F_XH);
        const uint32_t bBase = sb + ((seg == 1) ? F_H1L : F_H1H);
#pragma unroll
        for (int k16 = 0; k16 < 4; k16++) {
            uint32_t a[4], b[4][2];
            {
                int r = aRowH;
                uint32_t addr = aBase + (uint32_t)r * 128 +
                                (uint32_t)(((k16 * 2 + aKh) ^ (r & 7)) * 16);
                ldsm_x4(a[0], a[1], a[2], a[3], addr);
            }
#pragma unroll
            for (int ni2 = 0; ni2 < 2; ni2++) {
                int n = bNh + ni2 * 16;
                uint32_t addr = bBase + (uint32_t)n * 128 +
                                (uint32_t)(((k16 * 2 + bKh) ^ (n & 7)) * 16);
                ldsm_x4(b[ni2 * 2][0], b[ni2 * 2][1],
                        b[ni2 * 2 + 1][0], b[ni2 * 2 + 1][1], addr);
            }
#pragma unroll
            for (int nb = 0; nb < 4; nb++)
                mma16816(hacc[nb], a, b[nb][0], b[nb][1]);
        }
    }

#pragma unroll
    for (int part = 0; part < 2; part++) {
        float partial = 0.0f;
#pragma unroll
        for (int nb = 0; nb < 4; nb++) {
#pragma unroll
            for (int i = 0; i < 2; i++) {
                int col = nb * 8 + (lane & 3) * 2 + i;
                float hv = fmaxf(hacc[nb][part * 2 + i] + sbh1[col], 0.0f);
                partial += hv * swh2[col];
            }
        }
        partial += __shfl_xor_sync(0xffffffffu, partial, 1);
        partial += __shfl_xor_sync(0xffffffffu, partial, 2);
        int row = rowBase + w * 16 + (lane >> 2) + part * 8;
        if ((lane & 3) == 0 && row < N) out[row] = partial + sbh2[0];
    }
}

// ---------------------------------------------------------------------------
// Launch: default stream, graph-capturable, no allocation, no sync.
// ---------------------------------------------------------------------------
extern "C" void kernel_launch(void* const* d_in, const int* in_sizes, int n_in,
                              void* d_out, int out_size)
{
    const float*     loc_x = (const float*)d_in[0];
    const float*     evt_x = (const float*)d_in[1];
    const long long* ei    = (const long long*)d_in[2];
    const float*     W_loc = (const float*)d_in[3];
    const float*     b_loc = (const float*)d_in[4];
    const float*     W_evt = (const float*)d_in[5];
    const float*     b_evt = (const float*)d_in[6];
    const float*     W_l   = (const float*)d_in[7];
    const float*     b_l   = (const float*)d_in[8];
    const float*     W_r   = (const float*)d_in[9];
    const float*     W_h1  = (const float*)d_in[10];
    const float*     b_h1  = (const float*)d_in[11];
    const float*     W_h2  = (const float*)d_in[12];
    const float*     b_h2  = (const float*)d_in[13];
    float* out = (float*)d_out;

    int NL = in_sizes[0] / 128;   // 100000
    int NE = in_sizes[1] / 128;   // 200000
    int E  = in_sizes[2] / 2;     // 1000000
    if (NL > MAX_LOC) NL = MAX_LOC;
    if (NE > MAX_EVT) NE = MAX_EVT;

    cudaFuncSetAttribute(proj_evt_zero_kernel,
                         cudaFuncAttributeMaxDynamicSharedMemorySize, PROJ_SMEM);
    cudaFuncSetAttribute(proj_loc_scatter_kernel,
                         cudaFuncAttributeMaxDynamicSharedMemorySize, PROJ_SMEM);
    cudaFuncSetAttribute(fused_mma_kernel,
                         cudaFuncAttributeMaxDynamicSharedMemorySize, FUSEDM_SMEM);

    // K1: weights pre-split + dtype detect (53 blocks)
    prep_kernel<<<53, 256>>>(ei, W_loc, W_evt, W_l, W_r, W_h1);

    int nA = (NL + 127) / 128;            // 782 loc tiles
    int nB = (NE + 127) / 128;            // 1563 evt tiles
    int n4 = NL * 16;
    int zb = (n4 + 255) / 256;            // 6250 zero blocks

    // K2: evt projection ∥ msg/cnt zeroing
    proj_evt_zero_kernel<<<nB + zb, 256, PROJ_SMEM>>>(evt_x, b_evt, NE, nB,
                                                      n4, NL);

    // K3: loc projection ∥ edge scatter
    int groups = (E + 3) / 4;
    long sc_threads = (long)groups * 16;
    int scB = (int)((sc_threads + 255) / 256);
    proj_loc_scatter_kernel<<<nA + scB, 256, PROJ_SMEM>>>(loc_x, b_loc, NL, nA,
                                                          ei, E, NL);

    // K4: fused SAGE + head
    fused_mma_kernel<<<nA, 256, FUSEDM_SMEM>>>(b_l, b_h1, W_h2, b_h2, out, NL);
}